// round 1
// baseline (speedup 1.0000x reference)
#include <cuda_runtime.h>

// Problem shapes (fixed for this problem instance)
#define BQ 8192   // queries
#define DD 512    // feature dim
#define PK 4096   // keys / prototypes
#define CC 1000   // output classes

#define EPS_F 1e-3f

// Scratch (device globals: allocation-free per harness rules)
__device__ float g_W[(size_t)BQ * PK];     // unnormalized attention weights
__device__ float g_inv_rowsum[BQ];
__device__ float g_xn2[BQ];
__device__ float g_kn2[PK];

// ---------------------------------------------------------------------------
// Squared row norms: one block per row, 128 threads
// which==0 -> g_xn2, which==1 -> g_kn2
// ---------------------------------------------------------------------------
__global__ void row_norm2_kernel(const float* __restrict__ X, int D, int which) {
    int row = blockIdx.x;
    const float* x = X + (size_t)row * D;
    float s = 0.f;
    for (int i = threadIdx.x; i < D; i += blockDim.x) {
        float v = x[i];
        s = fmaf(v, v, s);
    }
    #pragma unroll
    for (int o = 16; o > 0; o >>= 1) s += __shfl_xor_sync(0xffffffffu, s, o);
    __shared__ float red[4];
    if ((threadIdx.x & 31) == 0) red[threadIdx.x >> 5] = s;
    __syncthreads();
    if (threadIdx.x == 0) {
        float t = red[0] + red[1] + red[2] + red[3];
        if (which == 0) g_xn2[row] = t;
        else            g_kn2[row] = t;
    }
}

// ---------------------------------------------------------------------------
// GEMM1: S = X @ K^T, fused epilogue W = 1/(EPS + relu(xn2 + kn2 - 2 S))
// 128x128 tile, BK=8, 256 threads, 8x8 microtile (split 4+4 for LDS.128)
// ---------------------------------------------------------------------------
__global__ void __launch_bounds__(256) gemm1_kernel(const float* __restrict__ X,
                                                    const float* __restrict__ Km) {
    __shared__ float As[8][128];
    __shared__ float Bs[8][128];

    const int bm = blockIdx.y * 128;
    const int bn = blockIdx.x * 128;
    const int tid = threadIdx.x;
    const int tx = tid & 15;   // 0..15
    const int ty = tid >> 4;   // 0..15

    const int lm = tid >> 1;          // 0..127 : row within tile to load
    const int lk = (tid & 1) * 4;     // 0 or 4 : k offset (float4)

    float acc[8][8];
    #pragma unroll
    for (int i = 0; i < 8; i++)
        #pragma unroll
        for (int j = 0; j < 8; j++) acc[i][j] = 0.f;

    for (int kt = 0; kt < DD; kt += 8) {
        float4 av = *reinterpret_cast<const float4*>(&X [(size_t)(bm + lm) * DD + kt + lk]);
        float4 bv = *reinterpret_cast<const float4*>(&Km[(size_t)(bn + lm) * DD + kt + lk]);
        As[lk + 0][lm] = av.x; As[lk + 1][lm] = av.y; As[lk + 2][lm] = av.z; As[lk + 3][lm] = av.w;
        Bs[lk + 0][lm] = bv.x; Bs[lk + 1][lm] = bv.y; Bs[lk + 2][lm] = bv.z; Bs[lk + 3][lm] = bv.w;
        __syncthreads();
        #pragma unroll
        for (int k = 0; k < 8; k++) {
            float a[8], b[8];
            *reinterpret_cast<float4*>(&a[0]) = *reinterpret_cast<const float4*>(&As[k][ty * 4]);
            *reinterpret_cast<float4*>(&a[4]) = *reinterpret_cast<const float4*>(&As[k][64 + ty * 4]);
            *reinterpret_cast<float4*>(&b[0]) = *reinterpret_cast<const float4*>(&Bs[k][tx * 4]);
            *reinterpret_cast<float4*>(&b[4]) = *reinterpret_cast<const float4*>(&Bs[k][64 + tx * 4]);
            #pragma unroll
            for (int i = 0; i < 8; i++)
                #pragma unroll
                for (int j = 0; j < 8; j++)
                    acc[i][j] = fmaf(a[i], b[j], acc[i][j]);
        }
        __syncthreads();
    }

    // Epilogue: W = 1/(EPS + relu(xn2 + kn2 - 2 acc))
    float kn[8];
    #pragma unroll
    for (int j = 0; j < 8; j++) {
        int n = (j < 4) ? (tx * 4 + j) : (64 + tx * 4 + (j - 4));
        kn[j] = g_kn2[bn + n];
    }
    #pragma unroll
    for (int i = 0; i < 8; i++) {
        int mi = (i < 4) ? (ty * 4 + i) : (64 + ty * 4 + (i - 4));
        int m = bm + mi;
        float xn = g_xn2[m];
        float w0[4], w1[4];
        #pragma unroll
        for (int j = 0; j < 4; j++) {
            float sq = fmaf(-2.f, acc[i][j], xn + kn[j]);
            w0[j] = 1.f / (EPS_F + fmaxf(sq, 0.f));
        }
        #pragma unroll
        for (int j = 4; j < 8; j++) {
            float sq = fmaf(-2.f, acc[i][j], xn + kn[j]);
            w1[j - 4] = 1.f / (EPS_F + fmaxf(sq, 0.f));
        }
        *reinterpret_cast<float4*>(&g_W[(size_t)m * PK + bn + tx * 4])      = *reinterpret_cast<float4*>(w0);
        *reinterpret_cast<float4*>(&g_W[(size_t)m * PK + bn + 64 + tx * 4]) = *reinterpret_cast<float4*>(w1);
    }
}

// ---------------------------------------------------------------------------
// Row sums of W -> reciprocal. One block per row, 256 threads, float4 loads.
// ---------------------------------------------------------------------------
__global__ void rowsum_kernel() {
    int row = blockIdx.x;
    const float4* w = reinterpret_cast<const float4*>(&g_W[(size_t)row * PK]);
    float s = 0.f;
    for (int i = threadIdx.x; i < PK / 4; i += 256) {
        float4 v = w[i];
        s += (v.x + v.y) + (v.z + v.w);
    }
    #pragma unroll
    for (int o = 16; o > 0; o >>= 1) s += __shfl_xor_sync(0xffffffffu, s, o);
    __shared__ float red[8];
    if ((threadIdx.x & 31) == 0) red[threadIdx.x >> 5] = s;
    __syncthreads();
    if (threadIdx.x == 0) {
        float t = 0.f;
        #pragma unroll
        for (int i = 0; i < 8; i++) t += red[i];
        g_inv_rowsum[row] = 1.f / t;
    }
}

// ---------------------------------------------------------------------------
// GEMM2: O = (W @ V) * inv_rowsum[m].  M=BQ, N=CC (bounds-checked), K=PK
// ---------------------------------------------------------------------------
__global__ void __launch_bounds__(256) gemm2_kernel(const float* __restrict__ V,
                                                    float* __restrict__ O) {
    __shared__ float As[8][128];
    __shared__ float Bs[8][128];

    const int bm = blockIdx.y * 128;
    const int bn = blockIdx.x * 128;
    const int tid = threadIdx.x;
    const int tx = tid & 15;
    const int ty = tid >> 4;

    const int lmA = tid >> 1;
    const int lkA = (tid & 1) * 4;
    const int lkB = tid >> 5;          // 0..7
    const int lnB = (tid & 31) * 4;    // 0..124

    float acc[8][8];
    #pragma unroll
    for (int i = 0; i < 8; i++)
        #pragma unroll
        for (int j = 0; j < 8; j++) acc[i][j] = 0.f;

    for (int kt = 0; kt < PK; kt += 8) {
        float4 av = *reinterpret_cast<const float4*>(&g_W[(size_t)(bm + lmA) * PK + kt + lkA]);
        As[lkA + 0][lmA] = av.x; As[lkA + 1][lmA] = av.y; As[lkA + 2][lmA] = av.z; As[lkA + 3][lmA] = av.w;
        float4 bv = make_float4(0.f, 0.f, 0.f, 0.f);
        if (bn + lnB < CC)
            bv = *reinterpret_cast<const float4*>(&V[(size_t)(kt + lkB) * CC + bn + lnB]);
        *reinterpret_cast<float4*>(&Bs[lkB][lnB]) = bv;
        __syncthreads();
        #pragma unroll
        for (int k = 0; k < 8; k++) {
            float a[8], b[8];
            *reinterpret_cast<float4*>(&a[0]) = *reinterpret_cast<const float4*>(&As[k][ty * 4]);
            *reinterpret_cast<float4*>(&a[4]) = *reinterpret_cast<const float4*>(&As[k][64 + ty * 4]);
            *reinterpret_cast<float4*>(&b[0]) = *reinterpret_cast<const float4*>(&Bs[k][tx * 4]);
            *reinterpret_cast<float4*>(&b[4]) = *reinterpret_cast<const float4*>(&Bs[k][64 + tx * 4]);
            #pragma unroll
            for (int i = 0; i < 8; i++)
                #pragma unroll
                for (int j = 0; j < 8; j++)
                    acc[i][j] = fmaf(a[i], b[j], acc[i][j]);
        }
        __syncthreads();
    }

    #pragma unroll
    for (int i = 0; i < 8; i++) {
        int mi = (i < 4) ? (ty * 4 + i) : (64 + ty * 4 + (i - 4));
        int m = bm + mi;
        float inv = g_inv_rowsum[m];
        #pragma unroll
        for (int j = 0; j < 8; j++) {
            int n = bn + ((j < 4) ? (tx * 4 + j) : (64 + tx * 4 + (j - 4)));
            if (n < CC) O[(size_t)m * CC + n] = acc[i][j] * inv;
        }
    }
}

// ---------------------------------------------------------------------------
extern "C" void kernel_launch(void* const* d_in, const int* in_sizes, int n_in,
                              void* d_out, int out_size) {
    const float* X = (const float*)d_in[0];   // [8192, 512]
    const float* K = (const float*)d_in[1];   // [4096, 512]
    const float* V = (const float*)d_in[2];   // [4096, 1000]
    float* O = (float*)d_out;                 // [8192, 1000]

    (void)in_sizes; (void)n_in; (void)out_size;

    row_norm2_kernel<<<BQ, 128>>>(X, DD, 0);
    row_norm2_kernel<<<PK, 128>>>(K, DD, 1);

    dim3 g1(PK / 128, BQ / 128);
    gemm1_kernel<<<g1, 256>>>(X, K);

    rowsum_kernel<<<BQ, 256>>>();

    dim3 g2((CC + 127) / 128, BQ / 128);
    gemm2_kernel<<<g2, 256>>>(V, O);
}

// round 2
// speedup vs baseline: 2.6478x; 2.6478x over previous
#include <cuda_runtime.h>
#include <cstdint>

#define BQ 8192   // queries
#define DD 512    // feature dim
#define PK 4096   // keys
#define CC 1000   // classes

#define EPS_F 1e-3f

// Scratch
__device__ float g_W[(size_t)BQ * PK];
__device__ float g_inv_rowsum[BQ];
__device__ float g_xn2[BQ];
__device__ float g_kn2[PK];

// ---------------------------------------------------------------------------
__device__ __forceinline__ uint32_t f2tf32(float f) {
    uint32_t u;
    asm("cvt.rna.tf32.f32 %0, %1;" : "=r"(u) : "f"(f));
    return u;
}

__device__ __forceinline__ void mma_tf32(float* c, const uint32_t* a, const uint32_t* b) {
    asm volatile(
        "mma.sync.aligned.m16n8k8.row.col.f32.tf32.tf32.f32 "
        "{%0,%1,%2,%3},{%4,%5,%6,%7},{%8,%9},{%0,%1,%2,%3};"
        : "+f"(c[0]), "+f"(c[1]), "+f"(c[2]), "+f"(c[3])
        : "r"(a[0]), "r"(a[1]), "r"(a[2]), "r"(a[3]), "r"(b[0]), "r"(b[1]));
}

// ---------------------------------------------------------------------------
// Row squared norms
// ---------------------------------------------------------------------------
__global__ void row_norm2_kernel(const float* __restrict__ X, int D, int which) {
    int row = blockIdx.x;
    const float* x = X + (size_t)row * D;
    float s = 0.f;
    for (int i = threadIdx.x; i < D; i += blockDim.x) {
        float v = x[i];
        s = fmaf(v, v, s);
    }
    #pragma unroll
    for (int o = 16; o > 0; o >>= 1) s += __shfl_xor_sync(0xffffffffu, s, o);
    __shared__ float red[4];
    if ((threadIdx.x & 31) == 0) red[threadIdx.x >> 5] = s;
    __syncthreads();
    if (threadIdx.x == 0) {
        float t = red[0] + red[1] + red[2] + red[3];
        if (which == 0) g_xn2[row] = t;
        else            g_kn2[row] = t;
    }
}

// ---------------------------------------------------------------------------
// GEMM1 (TF32 mma): S = X @ K^T, epilogue W = 1/(EPS + relu(xn2+kn2-2S))
// 128x128x16 tile, 256 threads, warp grid 2(m) x 4(n), warp tile 64x32.
// Smem: As[m][k] Lk=20, Bs[n][k] Lk=20 (tf32 bits).
// ---------------------------------------------------------------------------
#define LKA 20
__global__ void __launch_bounds__(256) gemm1_mma(const float* __restrict__ X,
                                                 const float* __restrict__ Km) {
    __shared__ uint32_t As[2][128 * LKA];
    __shared__ uint32_t Bs[2][128 * LKA];

    const int tid  = threadIdx.x;
    const int lane = tid & 31;
    const int wid  = tid >> 5;
    const int wm   = wid >> 2;   // 0..1
    const int wn   = wid & 3;    // 0..3
    const int bm   = blockIdx.y * 128;
    const int bn   = blockIdx.x * 128;

    // staging: 64 rows x 4 float4; two passes (rows +0, +64)
    const int lm  = tid >> 2;          // 0..63
    const int lk4 = (tid & 3) * 4;     // 0,4,8,12

    const float* pA0 = X  + (size_t)(bm + lm) * DD + lk4;
    const float* pA1 = pA0 + (size_t)64 * DD;
    const float* pB0 = Km + (size_t)(bn + lm) * DD + lk4;
    const float* pB1 = pB0 + (size_t)64 * DD;

    float4 ra0, ra1, rb0, rb1;
    ra0 = *reinterpret_cast<const float4*>(pA0);
    ra1 = *reinterpret_cast<const float4*>(pA1);
    rb0 = *reinterpret_cast<const float4*>(pB0);
    rb1 = *reinterpret_cast<const float4*>(pB1);

    float c[4][4][4];
    #pragma unroll
    for (int i = 0; i < 4; i++)
        #pragma unroll
        for (int j = 0; j < 4; j++)
            #pragma unroll
            for (int r = 0; r < 4; r++) c[i][j][r] = 0.f;

    const int sA0 = lm * LKA + lk4;
    const int sA1 = (lm + 64) * LKA + lk4;

    // fragment index bases
    const int fr = lane >> 2;   // 0..7
    const int fc = lane & 3;    // 0..3

    const int T = DD / 16;      // 32
    #pragma unroll 1
    for (int t = 0; t < T; t++) {
        // stage tile t into buf t&1
        {
            int buf = t & 1;
            uint4 u;
            u.x = f2tf32(ra0.x); u.y = f2tf32(ra0.y); u.z = f2tf32(ra0.z); u.w = f2tf32(ra0.w);
            *reinterpret_cast<uint4*>(&As[buf][sA0]) = u;
            u.x = f2tf32(ra1.x); u.y = f2tf32(ra1.y); u.z = f2tf32(ra1.z); u.w = f2tf32(ra1.w);
            *reinterpret_cast<uint4*>(&As[buf][sA1]) = u;
            u.x = f2tf32(rb0.x); u.y = f2tf32(rb0.y); u.z = f2tf32(rb0.z); u.w = f2tf32(rb0.w);
            *reinterpret_cast<uint4*>(&Bs[buf][sA0]) = u;
            u.x = f2tf32(rb1.x); u.y = f2tf32(rb1.y); u.z = f2tf32(rb1.z); u.w = f2tf32(rb1.w);
            *reinterpret_cast<uint4*>(&Bs[buf][sA1]) = u;
        }
        __syncthreads();
        // prefetch tile t+1
        if (t + 1 < T) {
            int off = (t + 1) * 16;
            ra0 = *reinterpret_cast<const float4*>(pA0 + off);
            ra1 = *reinterpret_cast<const float4*>(pA1 + off);
            rb0 = *reinterpret_cast<const float4*>(pB0 + off);
            rb1 = *reinterpret_cast<const float4*>(pB1 + off);
        }
        // compute tile t
        int buf = t & 1;
        #pragma unroll
        for (int ks = 0; ks < 2; ks++) {
            const int kk = ks * 8;
            uint32_t af[4][4], bf[4][2];
            #pragma unroll
            for (int mt = 0; mt < 4; mt++) {
                int base = (wm * 64 + mt * 16 + fr) * LKA + kk + fc;
                af[mt][0] = As[buf][base];
                af[mt][1] = As[buf][base + 8 * LKA];
                af[mt][2] = As[buf][base + 4];
                af[mt][3] = As[buf][base + 8 * LKA + 4];
            }
            #pragma unroll
            for (int nt = 0; nt < 4; nt++) {
                int base = (wn * 32 + nt * 8 + fr) * LKA + kk + fc;
                bf[nt][0] = Bs[buf][base];
                bf[nt][1] = Bs[buf][base + 4];
            }
            #pragma unroll
            for (int mt = 0; mt < 4; mt++)
                #pragma unroll
                for (int nt = 0; nt < 4; nt++)
                    mma_tf32(c[mt][nt], af[mt], bf[nt]);
        }
        __syncthreads();
    }

    // Epilogue: W = 1/(EPS + relu(xn2 + kn2 - 2 S))
    #pragma unroll
    for (int mt = 0; mt < 4; mt++) {
        int row0 = bm + wm * 64 + mt * 16 + fr;
        float xn0 = g_xn2[row0];
        float xn1 = g_xn2[row0 + 8];
        #pragma unroll
        for (int nt = 0; nt < 4; nt++) {
            int col = bn + wn * 32 + nt * 8 + 2 * fc;
            float kn0 = g_kn2[col];
            float kn1 = g_kn2[col + 1];
            float2 w0, w1;
            w0.x = 1.f / (EPS_F + fmaxf(fmaf(-2.f, c[mt][nt][0], xn0 + kn0), 0.f));
            w0.y = 1.f / (EPS_F + fmaxf(fmaf(-2.f, c[mt][nt][1], xn0 + kn1), 0.f));
            w1.x = 1.f / (EPS_F + fmaxf(fmaf(-2.f, c[mt][nt][2], xn1 + kn0), 0.f));
            w1.y = 1.f / (EPS_F + fmaxf(fmaf(-2.f, c[mt][nt][3], xn1 + kn1), 0.f));
            *reinterpret_cast<float2*>(&g_W[(size_t)row0 * PK + col])       = w0;
            *reinterpret_cast<float2*>(&g_W[(size_t)(row0 + 8) * PK + col]) = w1;
        }
    }
}

// ---------------------------------------------------------------------------
// Row sums of W -> reciprocal
// ---------------------------------------------------------------------------
__global__ void rowsum_kernel() {
    int row = blockIdx.x;
    const float4* w = reinterpret_cast<const float4*>(&g_W[(size_t)row * PK]);
    float s = 0.f;
    for (int i = threadIdx.x; i < PK / 4; i += 256) {
        float4 v = w[i];
        s += (v.x + v.y) + (v.z + v.w);
    }
    #pragma unroll
    for (int o = 16; o > 0; o >>= 1) s += __shfl_xor_sync(0xffffffffu, s, o);
    __shared__ float red[8];
    if ((threadIdx.x & 31) == 0) red[threadIdx.x >> 5] = s;
    __syncthreads();
    if (threadIdx.x == 0) {
        float t = 0.f;
        #pragma unroll
        for (int i = 0; i < 8; i++) t += red[i];
        g_inv_rowsum[row] = 1.f / t;
    }
}

// ---------------------------------------------------------------------------
// GEMM2 (TF32 mma): O = (W @ V) * inv_rowsum.  A = W [m][k], B = V [k][n].
// Smem: As[m][k] Lk=20, Bs[k][n] Ln=136.
// ---------------------------------------------------------------------------
#define LNB 136
__global__ void __launch_bounds__(256) gemm2_mma(const float* __restrict__ V,
                                                 float* __restrict__ O) {
    __shared__ uint32_t As[2][128 * LKA];
    __shared__ uint32_t Bs[2][16 * LNB];

    const int tid  = threadIdx.x;
    const int lane = tid & 31;
    const int wid  = tid >> 5;
    const int wm   = wid >> 2;
    const int wn   = wid & 3;
    const int bm   = blockIdx.y * 128;
    const int bn   = blockIdx.x * 128;

    // A staging (same as gemm1)
    const int lm  = tid >> 2;
    const int lk4 = (tid & 3) * 4;
    const float* pA0 = g_W + (size_t)(bm + lm) * PK + lk4;
    const float* pA1 = pA0 + (size_t)64 * PK;

    // B staging: 16 rows(k) x 128 cols(n); thread: k=tid>>5 (0..7, +8), n4=(tid&31)*4
    const int kb  = tid >> 5;
    const int ln4 = (tid & 31) * 4;
    const int colB = bn + ln4;
    const bool bval = (colB + 3) < CC;
    const float* pV0 = V + (size_t)kb * CC + colB;
    const float* pV1 = pV0 + (size_t)8 * CC;

    float4 ra0, ra1, rb0, rb1;
    ra0 = *reinterpret_cast<const float4*>(pA0);
    ra1 = *reinterpret_cast<const float4*>(pA1);
    rb0 = bval ? *reinterpret_cast<const float4*>(pV0) : make_float4(0.f, 0.f, 0.f, 0.f);
    rb1 = bval ? *reinterpret_cast<const float4*>(pV1) : make_float4(0.f, 0.f, 0.f, 0.f);

    float c[4][4][4];
    #pragma unroll
    for (int i = 0; i < 4; i++)
        #pragma unroll
        for (int j = 0; j < 4; j++)
            #pragma unroll
            for (int r = 0; r < 4; r++) c[i][j][r] = 0.f;

    const int sA0 = lm * LKA + lk4;
    const int sA1 = (lm + 64) * LKA + lk4;
    const int sB0 = kb * LNB + ln4;
    const int sB1 = (kb + 8) * LNB + ln4;

    const int fr = lane >> 2;
    const int fc = lane & 3;

    const int T = PK / 16;   // 256
    #pragma unroll 1
    for (int t = 0; t < T; t++) {
        {
            int buf = t & 1;
            uint4 u;
            u.x = f2tf32(ra0.x); u.y = f2tf32(ra0.y); u.z = f2tf32(ra0.z); u.w = f2tf32(ra0.w);
            *reinterpret_cast<uint4*>(&As[buf][sA0]) = u;
            u.x = f2tf32(ra1.x); u.y = f2tf32(ra1.y); u.z = f2tf32(ra1.z); u.w = f2tf32(ra1.w);
            *reinterpret_cast<uint4*>(&As[buf][sA1]) = u;
            u.x = f2tf32(rb0.x); u.y = f2tf32(rb0.y); u.z = f2tf32(rb0.z); u.w = f2tf32(rb0.w);
            *reinterpret_cast<uint4*>(&Bs[buf][sB0]) = u;
            u.x = f2tf32(rb1.x); u.y = f2tf32(rb1.y); u.z = f2tf32(rb1.z); u.w = f2tf32(rb1.w);
            *reinterpret_cast<uint4*>(&Bs[buf][sB1]) = u;
        }
        __syncthreads();
        if (t + 1 < T) {
            int off = (t + 1) * 16;
            ra0 = *reinterpret_cast<const float4*>(pA0 + off);
            ra1 = *reinterpret_cast<const float4*>(pA1 + off);
            rb0 = bval ? *reinterpret_cast<const float4*>(pV0 + (size_t)off * CC) : make_float4(0.f, 0.f, 0.f, 0.f);
            rb1 = bval ? *reinterpret_cast<const float4*>(pV1 + (size_t)off * CC) : make_float4(0.f, 0.f, 0.f, 0.f);
        }
        int buf = t & 1;
        #pragma unroll
        for (int ks = 0; ks < 2; ks++) {
            const int kk = ks * 8;
            uint32_t af[4][4], bf[4][2];
            #pragma unroll
            for (int mt = 0; mt < 4; mt++) {
                int base = (wm * 64 + mt * 16 + fr) * LKA + kk + fc;
                af[mt][0] = As[buf][base];
                af[mt][1] = As[buf][base + 8 * LKA];
                af[mt][2] = As[buf][base + 4];
                af[mt][3] = As[buf][base + 8 * LKA + 4];
            }
            #pragma unroll
            for (int nt = 0; nt < 4; nt++) {
                int base = (kk + fc) * LNB + wn * 32 + nt * 8 + fr;
                bf[nt][0] = Bs[buf][base];
                bf[nt][1] = Bs[buf][base + 4 * LNB];
            }
            #pragma unroll
            for (int mt = 0; mt < 4; mt++)
                #pragma unroll
                for (int nt = 0; nt < 4; nt++)
                    mma_tf32(c[mt][nt], af[mt], bf[nt]);
        }
        __syncthreads();
    }

    #pragma unroll
    for (int mt = 0; mt < 4; mt++) {
        int row0 = bm + wm * 64 + mt * 16 + fr;
        float inv0 = g_inv_rowsum[row0];
        float inv1 = g_inv_rowsum[row0 + 8];
        #pragma unroll
        for (int nt = 0; nt < 4; nt++) {
            int col = bn + wn * 32 + nt * 8 + 2 * fc;
            if (col < CC) {
                float2 o0, o1;
                o0.x = c[mt][nt][0] * inv0;
                o0.y = c[mt][nt][1] * inv0;
                o1.x = c[mt][nt][2] * inv1;
                o1.y = c[mt][nt][3] * inv1;
                *reinterpret_cast<float2*>(&O[(size_t)row0 * CC + col])       = o0;
                *reinterpret_cast<float2*>(&O[(size_t)(row0 + 8) * CC + col]) = o1;
            }
        }
    }
}

// ---------------------------------------------------------------------------
extern "C" void kernel_launch(void* const* d_in, const int* in_sizes, int n_in,
                              void* d_out, int out_size) {
    const float* X = (const float*)d_in[0];
    const float* K = (const float*)d_in[1];
    const float* V = (const float*)d_in[2];
    float* O = (float*)d_out;
    (void)in_sizes; (void)n_in; (void)out_size;

    row_norm2_kernel<<<BQ, 128>>>(X, DD, 0);
    row_norm2_kernel<<<PK, 128>>>(K, DD, 1);

    dim3 g1(PK / 128, BQ / 128);
    gemm1_mma<<<g1, 256>>>(X, K);

    rowsum_kernel<<<BQ, 256>>>();

    dim3 g2((CC + 127) / 128, BQ / 128);
    gemm2_mma<<<g2, 256>>>(V, O);
}

// round 5
// speedup vs baseline: 4.1617x; 1.5717x over previous
#include <cuda_runtime.h>
#include <cuda_fp16.h>
#include <cstdint>

#define BQ 8192
#define DD 512
#define PK 4096
#define CC 1000
#define NPAD 1024
#define EPS_F 1e-3f

// ---------------- scratch ----------------
__device__ __align__(16) __half g_Wh[(size_t)BQ * PK];
__device__ __align__(16) __half g_Vth[(size_t)NPAD * PK];
__device__ float g_inv_rowsum[BQ];
__device__ float g_xn2[BQ];
__device__ float g_kn2[PK];

// ---------------- helpers ----------------
__device__ __forceinline__ uint32_t pack_h2(float a, float b) {
    __half2 h = __floats2half2_rn(a, b);
    return *reinterpret_cast<uint32_t*>(&h);
}

__device__ __forceinline__ void mma_f16(float* c, const uint32_t* a, const uint32_t* b) {
    asm volatile(
        "mma.sync.aligned.m16n8k16.row.col.f32.f16.f16.f32 "
        "{%0,%1,%2,%3},{%4,%5,%6,%7},{%8,%9},{%0,%1,%2,%3};"
        : "+f"(c[0]), "+f"(c[1]), "+f"(c[2]), "+f"(c[3])
        : "r"(a[0]), "r"(a[1]), "r"(a[2]), "r"(a[3]), "r"(b[0]), "r"(b[1]));
}

#define PITCH 12   // u32 per smem row: 8 data (16 halves) + 4 pad; 12*fr mod 32 all-distinct

// ---------------- small kernels ----------------
__global__ void row_norm2_kernel(const float* __restrict__ X, int D, int which) {
    int row = blockIdx.x;
    const float* x = X + (size_t)row * D;
    float s = 0.f;
    for (int i = threadIdx.x; i < D; i += blockDim.x) { float v = x[i]; s = fmaf(v, v, s); }
    #pragma unroll
    for (int o = 16; o > 0; o >>= 1) s += __shfl_xor_sync(0xffffffffu, s, o);
    __shared__ float red[4];
    if ((threadIdx.x & 31) == 0) red[threadIdx.x >> 5] = s;
    __syncthreads();
    if (threadIdx.x == 0) {
        float t = red[0] + red[1] + red[2] + red[3];
        if (which == 0) g_xn2[row] = t; else g_kn2[row] = t;
    }
}

__global__ void transpose_vh_kernel(const float* __restrict__ V) {
    __shared__ float t[32][33];
    int nb = blockIdx.x * 32, kb = blockIdx.y * 32;
    int tx = threadIdx.x, ty = threadIdx.y;
    #pragma unroll
    for (int i = 0; i < 32; i += 8) {
        float v = 0.f;
        if (nb + tx < CC) v = V[(size_t)(kb + ty + i) * CC + nb + tx];
        t[ty + i][tx] = v;
    }
    __syncthreads();
    #pragma unroll
    for (int i = 0; i < 32; i += 8)
        g_Vth[(size_t)(nb + ty + i) * PK + kb + tx] = __float2half_rn(t[tx][ty + i]);
}

// Row sums of half W (sums the exact GEMM2 operand values)
__global__ void rowsum_h_kernel() {
    int row = blockIdx.x;
    const uint4* w = reinterpret_cast<const uint4*>(&g_Wh[(size_t)row * PK]);
    float s = 0.f;
    for (int i = threadIdx.x; i < PK / 8; i += 256) {
        uint4 u = w[i];
        const __half2* h = reinterpret_cast<const __half2*>(&u);
        #pragma unroll
        for (int j = 0; j < 4; j++) {
            float2 f = __half22float2(h[j]);
            s += f.x + f.y;
        }
    }
    #pragma unroll
    for (int o = 16; o > 0; o >>= 1) s += __shfl_xor_sync(0xffffffffu, s, o);
    __shared__ float red[8];
    if ((threadIdx.x & 31) == 0) red[threadIdx.x >> 5] = s;
    __syncthreads();
    if (threadIdx.x == 0) {
        float t = 0.f;
        #pragma unroll
        for (int i = 0; i < 8; i++) t += red[i];
        g_inv_rowsum[row] = 1.f / t;
    }
}

// ---------------------------------------------------------------------------
// GEMM1 (f16 mma): S = X @ K^T, epilogue W = 1/(EPS + relu(xn2+kn2-2S)) -> half
// 128x128x16 tile, 256 threads, warp grid 2(m) x 4(n), warp tile 64x32.
// Round-2 skeleton: register prefetch, double buffer, convert at smem store.
// ---------------------------------------------------------------------------
__global__ void __launch_bounds__(256) gemm1_h(const float* __restrict__ X,
                                               const float* __restrict__ Km) {
    __shared__ uint32_t As[2][128 * PITCH];
    __shared__ uint32_t Bs[2][128 * PITCH];

    const int tid  = threadIdx.x;
    const int lane = tid & 31;
    const int wid  = tid >> 5;
    const int wm   = wid >> 2;   // 0..1
    const int wn   = wid & 3;    // 0..3
    const int bm   = blockIdx.y * 128;
    const int bn   = blockIdx.x * 128;

    // staging: 64 rows x 4 float4; two passes (rows +0, +64)
    const int lm  = tid >> 2;          // 0..63
    const int lk4 = (tid & 3) * 4;     // 0,4,8,12 (floats)

    const float* pA0 = X  + (size_t)(bm + lm) * DD + lk4;
    const float* pA1 = pA0 + (size_t)64 * DD;
    const float* pB0 = Km + (size_t)(bn + lm) * DD + lk4;
    const float* pB1 = pB0 + (size_t)64 * DD;

    float4 ra0 = *reinterpret_cast<const float4*>(pA0);
    float4 ra1 = *reinterpret_cast<const float4*>(pA1);
    float4 rb0 = *reinterpret_cast<const float4*>(pB0);
    float4 rb1 = *reinterpret_cast<const float4*>(pB1);

    float c[4][4][4];
    #pragma unroll
    for (int i = 0; i < 4; i++)
        #pragma unroll
        for (int j = 0; j < 4; j++)
            #pragma unroll
            for (int r = 0; r < 4; r++) c[i][j][r] = 0.f;

    const int sA0 = lm * PITCH + (tid & 3) * 2;
    const int sA1 = (lm + 64) * PITCH + (tid & 3) * 2;

    const int fr = lane >> 2;   // 0..7
    const int fc = lane & 3;    // 0..3

    const int T = DD / 16;      // 32
    #pragma unroll 1
    for (int t = 0; t < T; t++) {
        int buf = t & 1;
        {
            uint2 u;
            u.x = pack_h2(ra0.x, ra0.y); u.y = pack_h2(ra0.z, ra0.w);
            *reinterpret_cast<uint2*>(&As[buf][sA0]) = u;
            u.x = pack_h2(ra1.x, ra1.y); u.y = pack_h2(ra1.z, ra1.w);
            *reinterpret_cast<uint2*>(&As[buf][sA1]) = u;
            u.x = pack_h2(rb0.x, rb0.y); u.y = pack_h2(rb0.z, rb0.w);
            *reinterpret_cast<uint2*>(&Bs[buf][sA0]) = u;
            u.x = pack_h2(rb1.x, rb1.y); u.y = pack_h2(rb1.z, rb1.w);
            *reinterpret_cast<uint2*>(&Bs[buf][sA1]) = u;
        }
        __syncthreads();
        if (t + 1 < T) {
            int off = (t + 1) * 16;
            ra0 = *reinterpret_cast<const float4*>(pA0 + off);
            ra1 = *reinterpret_cast<const float4*>(pA1 + off);
            rb0 = *reinterpret_cast<const float4*>(pB0 + off);
            rb1 = *reinterpret_cast<const float4*>(pB1 + off);
        }
        {
            uint32_t af[4][4], bf[4][2];
            #pragma unroll
            for (int mt = 0; mt < 4; mt++) {
                int base = (wm * 64 + mt * 16 + fr) * PITCH + fc;
                af[mt][0] = As[buf][base];
                af[mt][1] = As[buf][base + 8 * PITCH];
                af[mt][2] = As[buf][base + 4];
                af[mt][3] = As[buf][base + 8 * PITCH + 4];
            }
            #pragma unroll
            for (int nt = 0; nt < 4; nt++) {
                int base = (wn * 32 + nt * 8 + fr) * PITCH + fc;
                bf[nt][0] = Bs[buf][base];
                bf[nt][1] = Bs[buf][base + 4];
            }
            #pragma unroll
            for (int mt = 0; mt < 4; mt++)
                #pragma unroll
                for (int nt = 0; nt < 4; nt++)
                    mma_f16(c[mt][nt], af[mt], bf[nt]);
        }
        __syncthreads();
    }

    // Epilogue: W = 1/(EPS + relu(xn2 + kn2 - 2 S)) stored as half
    #pragma unroll
    for (int mt = 0; mt < 4; mt++) {
        int row0 = bm + wm * 64 + mt * 16 + fr;
        float xn0 = g_xn2[row0];
        float xn1 = g_xn2[row0 + 8];
        #pragma unroll
        for (int nt = 0; nt < 4; nt++) {
            int col = bn + wn * 32 + nt * 8 + 2 * fc;
            float kn0 = g_kn2[col], kn1 = g_kn2[col + 1];
            float w00 = 1.f / (EPS_F + fmaxf(fmaf(-2.f, c[mt][nt][0], xn0 + kn0), 0.f));
            float w01 = 1.f / (EPS_F + fmaxf(fmaf(-2.f, c[mt][nt][1], xn0 + kn1), 0.f));
            float w10 = 1.f / (EPS_F + fmaxf(fmaf(-2.f, c[mt][nt][2], xn1 + kn0), 0.f));
            float w11 = 1.f / (EPS_F + fmaxf(fmaf(-2.f, c[mt][nt][3], xn1 + kn1), 0.f));
            __half2 h0 = __floats2half2_rn(w00, w01);
            __half2 h1 = __floats2half2_rn(w10, w11);
            *reinterpret_cast<__half2*>(&g_Wh[(size_t)row0 * PK + col])       = h0;
            *reinterpret_cast<__half2*>(&g_Wh[(size_t)(row0 + 8) * PK + col]) = h1;
        }
    }
}

// ---------------------------------------------------------------------------
// GEMM2 (f16 mma): O = (Wh @ Vth^T) * inv_rowsum.  A = Wh [m][k], B = Vth [n][k],
// both already half: staging is a plain copy. Same skeleton.
// ---------------------------------------------------------------------------
__global__ void __launch_bounds__(256) gemm2_h(float* __restrict__ O) {
    __shared__ uint32_t As[2][128 * PITCH];
    __shared__ uint32_t Bs[2][128 * PITCH];

    const int tid  = threadIdx.x;
    const int lane = tid & 31;
    const int wid  = tid >> 5;
    const int wm   = wid >> 2;
    const int wn   = wid & 3;
    const int bm   = blockIdx.y * 128;
    const int bn   = blockIdx.x * 128;

    // staging: 128 rows x 2 x uint4 (8 halves each); thread: row=tid>>1, half-off=(tid&1)*8
    const int lr  = tid >> 1;          // 0..127
    const int lo  = (tid & 1) * 8;     // halves

    const __half* pA = g_Wh  + (size_t)(bm + lr) * PK + lo;
    const __half* pB = g_Vth + (size_t)(bn + lr) * PK + lo;

    uint4 ra = *reinterpret_cast<const uint4*>(pA);
    uint4 rb = *reinterpret_cast<const uint4*>(pB);

    float c[4][4][4];
    #pragma unroll
    for (int i = 0; i < 4; i++)
        #pragma unroll
        for (int j = 0; j < 4; j++)
            #pragma unroll
            for (int r = 0; r < 4; r++) c[i][j][r] = 0.f;

    const int sA = lr * PITCH + (tid & 1) * 4;

    const int fr = lane >> 2;
    const int fc = lane & 3;

    const int T = PK / 16;   // 256
    #pragma unroll 1
    for (int t = 0; t < T; t++) {
        int buf = t & 1;
        *reinterpret_cast<uint4*>(&As[buf][sA]) = ra;
        *reinterpret_cast<uint4*>(&Bs[buf][sA]) = rb;
        __syncthreads();
        if (t + 1 < T) {
            int off = (t + 1) * 16;   // halves
            ra = *reinterpret_cast<const uint4*>(pA + off);
            rb = *reinterpret_cast<const uint4*>(pB + off);
        }
        {
            uint32_t af[4][4], bf[4][2];
            #pragma unroll
            for (int mt = 0; mt < 4; mt++) {
                int base = (wm * 64 + mt * 16 + fr) * PITCH + fc;
                af[mt][0] = As[buf][base];
                af[mt][1] = As[buf][base + 8 * PITCH];
                af[mt][2] = As[buf][base + 4];
                af[mt][3] = As[buf][base + 8 * PITCH + 4];
            }
            #pragma unroll
            for (int nt = 0; nt < 4; nt++) {
                int base = (wn * 32 + nt * 8 + fr) * PITCH + fc;
                bf[nt][0] = Bs[buf][base];
                bf[nt][1] = Bs[buf][base + 4];
            }
            #pragma unroll
            for (int mt = 0; mt < 4; mt++)
                #pragma unroll
                for (int nt = 0; nt < 4; nt++)
                    mma_f16(c[mt][nt], af[mt], bf[nt]);
        }
        __syncthreads();
    }

    #pragma unroll
    for (int mt = 0; mt < 4; mt++) {
        int row0 = bm + wm * 64 + mt * 16 + fr;
        float inv0 = g_inv_rowsum[row0];
        float inv1 = g_inv_rowsum[row0 + 8];
        #pragma unroll
        for (int nt = 0; nt < 4; nt++) {
            int col = bn + wn * 32 + nt * 8 + 2 * fc;
            if (col < CC) {
                float2 o0, o1;
                o0.x = c[mt][nt][0] * inv0; o0.y = c[mt][nt][1] * inv0;
                o1.x = c[mt][nt][2] * inv1; o1.y = c[mt][nt][3] * inv1;
                *reinterpret_cast<float2*>(&O[(size_t)row0 * CC + col])       = o0;
                *reinterpret_cast<float2*>(&O[(size_t)(row0 + 8) * CC + col]) = o1;
            }
        }
    }
}

// ---------------------------------------------------------------------------
extern "C" void kernel_launch(void* const* d_in, const int* in_sizes, int n_in,
                              void* d_out, int out_size) {
    const float* X = (const float*)d_in[0];
    const float* K = (const float*)d_in[1];
    const float* V = (const float*)d_in[2];
    float* O = (float*)d_out;
    (void)in_sizes; (void)n_in; (void)out_size;

    row_norm2_kernel<<<BQ, 128>>>(X, DD, 0);
    row_norm2_kernel<<<PK, 128>>>(K, DD, 1);
    transpose_vh_kernel<<<dim3(NPAD / 32, PK / 32), dim3(32, 8)>>>(V);

    gemm1_h<<<dim3(PK / 128, BQ / 128), 256>>>(X, K);

    rowsum_h_kernel<<<BQ, 256>>>();

    gemm2_h<<<dim3((CC + 127) / 128, BQ / 128), 256>>>(O);
}

// round 7
// speedup vs baseline: 4.9650x; 1.1930x over previous
#include <cuda_runtime.h>
#include <cuda_fp16.h>
#include <cstdint>

#define BQ 8192
#define DD 512
#define PK 4096
#define CC 1000
#define NPAD 1024
#define EPS_F 1e-3f

// ---------------- scratch ----------------
__device__ __align__(16) __half g_Wh[(size_t)BQ * PK];
__device__ __align__(16) __half g_Vth[(size_t)NPAD * PK];
__device__ float g_inv_rowsum[BQ];
__device__ float g_xn2[BQ];
__device__ float g_kn2[PK];

// ---------------- helpers ----------------
__device__ __forceinline__ uint32_t smem_u32(const void* p) {
    uint32_t a;
    asm("{ .reg .u64 t; cvta.to.shared.u64 t, %1; cvt.u32.u64 %0, t; }" : "=r"(a) : "l"(p));
    return a;
}

__device__ __forceinline__ uint32_t pack_h2(float a, float b) {
    __half2 h = __floats2half2_rn(a, b);
    return *reinterpret_cast<uint32_t*>(&h);
}

__device__ __forceinline__ void mma_f16(float* c, const uint32_t* a, const uint32_t* b) {
    asm volatile(
        "mma.sync.aligned.m16n8k16.row.col.f32.f16.f16.f32 "
        "{%0,%1,%2,%3},{%4,%5,%6,%7},{%8,%9},{%0,%1,%2,%3};"
        : "+f"(c[0]), "+f"(c[1]), "+f"(c[2]), "+f"(c[3])
        : "r"(a[0]), "r"(a[1]), "r"(a[2]), "r"(a[3]), "r"(b[0]), "r"(b[1]));
}

__device__ __forceinline__ void ldsm_x4(uint32_t* r, uint32_t addr) {
    asm volatile("ldmatrix.sync.aligned.m8n8.x4.shared.b16 {%0,%1,%2,%3}, [%4];"
        : "=r"(r[0]), "=r"(r[1]), "=r"(r[2]), "=r"(r[3]) : "r"(addr));
}

// smem tile: 128 rows x 32B (16 halves). byte(r,c,i) = r*32 + ((c ^ ((r>>2)&1))<<4) + i
// (c = 16B chunk 0/1). Verified: every ldmatrix 8-lane phase hits 8 distinct 16B groups.
#define ROWB   32
#define BUFB   4096            // 128 * 32

// ---------------- small kernels (R5 verbatim) ----------------
__global__ void row_norm2_kernel(const float* __restrict__ X, int D, int which) {
    int row = blockIdx.x;
    const float* x = X + (size_t)row * D;
    float s = 0.f;
    for (int i = threadIdx.x; i < D; i += blockDim.x) { float v = x[i]; s = fmaf(v, v, s); }
    #pragma unroll
    for (int o = 16; o > 0; o >>= 1) s += __shfl_xor_sync(0xffffffffu, s, o);
    __shared__ float red[4];
    if ((threadIdx.x & 31) == 0) red[threadIdx.x >> 5] = s;
    __syncthreads();
    if (threadIdx.x == 0) {
        float t = red[0] + red[1] + red[2] + red[3];
        if (which == 0) g_xn2[row] = t; else g_kn2[row] = t;
    }
}

__global__ void transpose_vh_kernel(const float* __restrict__ V) {
    __shared__ float t[32][33];
    int nb = blockIdx.x * 32, kb = blockIdx.y * 32;
    int tx = threadIdx.x, ty = threadIdx.y;
    #pragma unroll
    for (int i = 0; i < 32; i += 8) {
        float v = 0.f;
        if (nb + tx < CC) v = V[(size_t)(kb + ty + i) * CC + nb + tx];
        t[ty + i][tx] = v;
    }
    __syncthreads();
    #pragma unroll
    for (int i = 0; i < 32; i += 8)
        g_Vth[(size_t)(nb + ty + i) * PK + kb + tx] = __float2half_rn(t[tx][ty + i]);
}

__global__ void rowsum_h_kernel() {
    int row = blockIdx.x;
    const uint4* w = reinterpret_cast<const uint4*>(&g_Wh[(size_t)row * PK]);
    float s = 0.f;
    for (int i = threadIdx.x; i < PK / 8; i += 256) {
        uint4 u = w[i];
        const __half2* h = reinterpret_cast<const __half2*>(&u);
        #pragma unroll
        for (int j = 0; j < 4; j++) {
            float2 f = __half22float2(h[j]);
            s += f.x + f.y;
        }
    }
    #pragma unroll
    for (int o = 16; o > 0; o >>= 1) s += __shfl_xor_sync(0xffffffffu, s, o);
    __shared__ float red[8];
    if ((threadIdx.x & 31) == 0) red[threadIdx.x >> 5] = s;
    __syncthreads();
    if (threadIdx.x == 0) {
        float t = 0.f;
        #pragma unroll
        for (int i = 0; i < 8; i++) t += red[i];
        g_inv_rowsum[row] = 1.f / t;
    }
}

// ---------------------------------------------------------------------------
// Fragment loader: per-warp ldmatrix offsets (byte offsets inside one buffer)
// A (m16k16 per mt): lanes 0-7 rows 0-7 c0 | 8-15 rows 8-15 c0 | 16-23 rows 0-7 c1 | 24-31 rows 8-15 c1
// B (two n8k16 per load p): lanes 0-7 n-blk 2p c0 | 8-15 n-blk 2p c1 | 16-23 n-blk 2p+1 c0 | 24-31 c1
// ---------------------------------------------------------------------------
struct FragOffsets {
    uint32_t a[4];
    uint32_t b[2];
};

__device__ __forceinline__ FragOffsets make_frag_offsets(int lane, int wm, int wn) {
    FragOffsets fo;
    {
        int r0 = wm * 64 + (lane & 7) + ((lane >> 3) & 1) * 8;
        int c  = (lane >> 4) & 1;
        int sw = (r0 >> 2) & 1;                    // invariant under +16*mt
        #pragma unroll
        for (int mt = 0; mt < 4; mt++)
            fo.a[mt] = (uint32_t)(r0 + mt * 16) * ROWB + (uint32_t)((c ^ sw) << 4);
    }
    {
        int g = lane >> 3;
        int c = g & 1;
        #pragma unroll
        for (int p = 0; p < 2; p++) {
            int r = wn * 32 + (2 * p + (g >> 1)) * 8 + (lane & 7);
            fo.b[p] = (uint32_t)r * ROWB + (uint32_t)((c ^ ((r >> 2) & 1)) << 4);
        }
    }
    return fo;
}

__device__ __forceinline__ void compute_tile(uint32_t aB, uint32_t bB,
                                             const FragOffsets& fo, float c[4][4][4]) {
    uint32_t af[4][4], bq[2][4];
    #pragma unroll
    for (int mt = 0; mt < 4; mt++) ldsm_x4(af[mt], aB + fo.a[mt]);
    #pragma unroll
    for (int p = 0; p < 2; p++)   ldsm_x4(bq[p], bB + fo.b[p]);
    #pragma unroll
    for (int mt = 0; mt < 4; mt++)
        #pragma unroll
        for (int nt = 0; nt < 4; nt++)
            mma_f16(c[mt][nt], af[mt], &bq[nt >> 1][(nt & 1) * 2]);
}

// ---------------------------------------------------------------------------
// GEMM1: S = X @ K^T (float in, convert at STS), epilogue -> g_Wh (half)
// ---------------------------------------------------------------------------
__global__ void __launch_bounds__(256) gemm1_h(const float* __restrict__ X,
                                               const float* __restrict__ Km) {
    __shared__ __align__(16) uint8_t As[2][BUFB];
    __shared__ __align__(16) uint8_t Bs[2][BUFB];

    const int tid  = threadIdx.x;
    const int lane = tid & 31;
    const int wid  = tid >> 5;
    const int wm   = wid >> 2, wn = wid & 3;
    const int fr = lane >> 2, fc = lane & 3;
    const int bm = blockIdx.y * 128, bn = blockIdx.x * 128;

    // staging: lm = tid>>2 (rows lm, lm+64); thread covers 8B at chunk ch, half h8
    const int lm  = tid >> 2;
    const int lk4 = (tid & 3) * 4;                 // float index in row
    const int ch  = (tid & 3) >> 1;
    const int h8  = tid & 1;
    const int sw  = (lm >> 2) & 1;                 // same for lm and lm+64
    const uint32_t soA0 = (uint32_t)lm * ROWB        + (uint32_t)((ch ^ sw) << 4) + h8 * 8;
    const uint32_t soA1 = (uint32_t)(lm + 64) * ROWB + (uint32_t)((ch ^ sw) << 4) + h8 * 8;

    const float* pA0 = X  + (size_t)(bm + lm) * DD + lk4;
    const float* pA1 = pA0 + (size_t)64 * DD;
    const float* pB0 = Km + (size_t)(bn + lm) * DD + lk4;
    const float* pB1 = pB0 + (size_t)64 * DD;

    float4 ra0 = *reinterpret_cast<const float4*>(pA0);
    float4 ra1 = *reinterpret_cast<const float4*>(pA1);
    float4 rb0 = *reinterpret_cast<const float4*>(pB0);
    float4 rb1 = *reinterpret_cast<const float4*>(pB1);

    float c[4][4][4];
    #pragma unroll
    for (int i = 0; i < 4; i++)
        #pragma unroll
        for (int j = 0; j < 4; j++)
            #pragma unroll
            for (int r = 0; r < 4; r++) c[i][j][r] = 0.f;

    const FragOffsets fo = make_frag_offsets(lane, wm, wn);
    const uint32_t sbA = smem_u32(&As[0][0]);
    const uint32_t sbB = smem_u32(&Bs[0][0]);

    const int T = DD / 16;      // 32
    #pragma unroll 1
    for (int t = 0; t < T; t++) {
        int buf = t & 1;
        {
            uint2 u;
            u.x = pack_h2(ra0.x, ra0.y); u.y = pack_h2(ra0.z, ra0.w);
            *reinterpret_cast<uint2*>(&As[buf][soA0]) = u;
            u.x = pack_h2(ra1.x, ra1.y); u.y = pack_h2(ra1.z, ra1.w);
            *reinterpret_cast<uint2*>(&As[buf][soA1]) = u;
            u.x = pack_h2(rb0.x, rb0.y); u.y = pack_h2(rb0.z, rb0.w);
            *reinterpret_cast<uint2*>(&Bs[buf][soA0]) = u;
            u.x = pack_h2(rb1.x, rb1.y); u.y = pack_h2(rb1.z, rb1.w);
            *reinterpret_cast<uint2*>(&Bs[buf][soA1]) = u;
        }
        __syncthreads();
        if (t + 1 < T) {
            int off = (t + 1) * 16;
            ra0 = *reinterpret_cast<const float4*>(pA0 + off);
            ra1 = *reinterpret_cast<const float4*>(pA1 + off);
            rb0 = *reinterpret_cast<const float4*>(pB0 + off);
            rb1 = *reinterpret_cast<const float4*>(pB1 + off);
        }
        compute_tile(sbA + buf * BUFB, sbB + buf * BUFB, fo, c);
        __syncthreads();
    }

    // Epilogue (R5 verbatim)
    #pragma unroll
    for (int mt = 0; mt < 4; mt++) {
        int row0 = bm + wm * 64 + mt * 16 + fr;
        float xn0 = g_xn2[row0];
        float xn1 = g_xn2[row0 + 8];
        #pragma unroll
        for (int nt = 0; nt < 4; nt++) {
            int col = bn + wn * 32 + nt * 8 + 2 * fc;
            float kn0 = g_kn2[col], kn1 = g_kn2[col + 1];
            float w00 = 1.f / (EPS_F + fmaxf(fmaf(-2.f, c[mt][nt][0], xn0 + kn0), 0.f));
            float w01 = 1.f / (EPS_F + fmaxf(fmaf(-2.f, c[mt][nt][1], xn0 + kn1), 0.f));
            float w10 = 1.f / (EPS_F + fmaxf(fmaf(-2.f, c[mt][nt][2], xn1 + kn0), 0.f));
            float w11 = 1.f / (EPS_F + fmaxf(fmaf(-2.f, c[mt][nt][3], xn1 + kn1), 0.f));
            __half2 h0 = __floats2half2_rn(w00, w01);
            __half2 h1 = __floats2half2_rn(w10, w11);
            *reinterpret_cast<__half2*>(&g_Wh[(size_t)row0 * PK + col])       = h0;
            *reinterpret_cast<__half2*>(&g_Wh[(size_t)(row0 + 8) * PK + col]) = h1;
        }
    }
}

// ---------------------------------------------------------------------------
// GEMM2: O = (Wh @ Vth^T) * inv_rowsum. Half sources: staging is 16B copy.
// ---------------------------------------------------------------------------
__global__ void __launch_bounds__(256) gemm2_h(float* __restrict__ O) {
    __shared__ __align__(16) uint8_t As[2][BUFB];
    __shared__ __align__(16) uint8_t Bs[2][BUFB];

    const int tid  = threadIdx.x;
    const int lane = tid & 31;
    const int wid  = tid >> 5;
    const int wm   = wid >> 2, wn = wid & 3;
    const int fr = lane >> 2, fc = lane & 3;
    const int bm = blockIdx.y * 128, bn = blockIdx.x * 128;

    // staging: row lr = tid>>1, chunk ch = tid&1 (16B each)
    const int lr = tid >> 1;
    const int ch = tid & 1;
    const uint32_t soS = (uint32_t)lr * ROWB + (uint32_t)((ch ^ ((lr >> 2) & 1)) << 4);

    const __half* pA = g_Wh  + (size_t)(bm + lr) * PK + ch * 8;
    const __half* pB = g_Vth + (size_t)(bn + lr) * PK + ch * 8;

    uint4 ra = *reinterpret_cast<const uint4*>(pA);
    uint4 rb = *reinterpret_cast<const uint4*>(pB);

    float c[4][4][4];
    #pragma unroll
    for (int i = 0; i < 4; i++)
        #pragma unroll
        for (int j = 0; j < 4; j++)
            #pragma unroll
            for (int r = 0; r < 4; r++) c[i][j][r] = 0.f;

    const FragOffsets fo = make_frag_offsets(lane, wm, wn);
    const uint32_t sbA = smem_u32(&As[0][0]);
    const uint32_t sbB = smem_u32(&Bs[0][0]);

    const int T = PK / 16;   // 256
    #pragma unroll 1
    for (int t = 0; t < T; t++) {
        int buf = t & 1;
        *reinterpret_cast<uint4*>(&As[buf][soS]) = ra;
        *reinterpret_cast<uint4*>(&Bs[buf][soS]) = rb;
        __syncthreads();
        if (t + 1 < T) {
            int off = (t + 1) * 16;   // halves
            ra = *reinterpret_cast<const uint4*>(pA + off);
            rb = *reinterpret_cast<const uint4*>(pB + off);
        }
        compute_tile(sbA + buf * BUFB, sbB + buf * BUFB, fo, c);
        __syncthreads();
    }

    #pragma unroll
    for (int mt = 0; mt < 4; mt++) {
        int row0 = bm + wm * 64 + mt * 16 + fr;
        float inv0 = g_inv_rowsum[row0];
        float inv1 = g_inv_rowsum[row0 + 8];
        #pragma unroll
        for (int nt = 0; nt < 4; nt++) {
            int col = bn + wn * 32 + nt * 8 + 2 * fc;
            if (col < CC) {
                float2 o0, o1;
                o0.x = c[mt][nt][0] * inv0; o0.y = c[mt][nt][1] * inv0;
                o1.x = c[mt][nt][2] * inv1; o1.y = c[mt][nt][3] * inv1;
                *reinterpret_cast<float2*>(&O[(size_t)row0 * CC + col])       = o0;
                *reinterpret_cast<float2*>(&O[(size_t)(row0 + 8) * CC + col]) = o1;
            }
        }
    }
}

// ---------------------------------------------------------------------------
extern "C" void kernel_launch(void* const* d_in, const int* in_sizes, int n_in,
                              void* d_out, int out_size) {
    const float* X = (const float*)d_in[0];
    const float* K = (const float*)d_in[1];
    const float* V = (const float*)d_in[2];
    float* O = (float*)d_out;
    (void)in_sizes; (void)n_in; (void)out_size;

    row_norm2_kernel<<<BQ, 128>>>(X, DD, 0);
    row_norm2_kernel<<<PK, 128>>>(K, DD, 1);
    transpose_vh_kernel<<<dim3(NPAD / 32, PK / 32), dim3(32, 8)>>>(V);

    gemm1_h<<<dim3(PK / 128, BQ / 128), 256>>>(X, K);

    rowsum_h_kernel<<<BQ, 256>>>();

    gemm2_h<<<dim3((CC + 127) / 128, BQ / 128), 256>>>(O);
}